// round 6
// baseline (speedup 1.0000x reference)
#include <cuda_runtime.h>
#include <cstdint>
#include <cstddef>

// Problem constants
#define TT   1024
#define BB   512
#define II   32
#define HH   256
#define OO   32
#define KDIM 288      // H + I

#define NGRP 16       // batch groups (32 rows each)
#define BT   32       // batch rows per group
#define JT   32       // j-indices per CTA (lanes)
#define NTHR 256      // 8 warps: 4 batch-octets x 2 kh-halves

typedef unsigned long long ull;

// Persistent scratch (no allocation allowed)
__device__ __align__(16) float    g_h[2][NGRP][HH][BT];   // hidden state [par][grp][j][b]
__device__ unsigned               g_bar[NGRP];            // per-group monotonic barrier counters

__global__ void init_kernel() {
    int idx = blockIdx.x * blockDim.x + threadIdx.x;
    if (idx < NGRP * HH * BT) ((float*)g_h)[idx] = 0.0f;  // zero h^(0) (parity 0)
    if (idx < NGRP) g_bar[idx] = 0u;
}

__device__ __forceinline__ void ffma2(ull& acc, ull a, ull b) {
    asm("fma.rn.f32x2 %0, %1, %2, %0;" : "+l"(acc) : "l"(a), "l"(b));
}
__device__ __forceinline__ void add2(ull& a, ull b) {
    asm("add.rn.f32x2 %0, %0, %1;" : "+l"(a) : "l"(b));
}
__device__ __forceinline__ ull pack2(float a, float b) {
    ull r; asm("mov.b64 %0, {%1, %2};" : "=l"(r) : "f"(a), "f"(b)); return r;
}
__device__ __forceinline__ float2 unpack2(ull v) {
    float2 r; asm("mov.b64 {%0, %1}, %2;" : "=f"(r.x), "=f"(r.y) : "l"(v)); return r;
}
__device__ __forceinline__ unsigned ld_acquire_u32(const unsigned* p) {
    unsigned v;
    asm volatile("ld.acquire.gpu.u32 %0, [%1];" : "=r"(v) : "l"(p));
    return v;
}
__device__ __forceinline__ void red_release_add(unsigned* p, unsigned v) {
    asm volatile("red.release.gpu.global.add.u32 [%0], %1;" :: "l"(p), "r"(v) : "memory");
}
__device__ __forceinline__ float sigf(float x) {
    return __fdividef(1.0f, 1.0f + __expf(-x));
}
__device__ __forceinline__ float tanh_acc(float x) {
    float ax = fabsf(x);
    float e  = __expf(-2.0f * ax);                 // e in (0,1], no overflow
    float r  = __fdividef(1.0f - e, 1.0f + e);
    return copysignf(r, x);
}

// 16 packed FMAs: 4 gate rows (lane's j) x 8 batches (oct), one k
__device__ __forceinline__ void mac16(ull (&acc)[4][4], const float* wk, const float* hk) {
    float4 w4 = *(const float4*)wk;
    ulonglong2 h01 = *(const ulonglong2*)hk;
    ulonglong2 h23 = *(const ulonglong2*)(hk + 4);
    ull w0 = pack2(w4.x, w4.x), w1 = pack2(w4.y, w4.y);
    ull w2 = pack2(w4.z, w4.z), w3 = pack2(w4.w, w4.w);
    ffma2(acc[0][0], h01.x, w0); ffma2(acc[0][1], h01.y, w0);
    ffma2(acc[0][2], h23.x, w0); ffma2(acc[0][3], h23.y, w0);
    ffma2(acc[1][0], h01.x, w1); ffma2(acc[1][1], h01.y, w1);
    ffma2(acc[1][2], h23.x, w1); ffma2(acc[1][3], h23.y, w1);
    ffma2(acc[2][0], h01.x, w2); ffma2(acc[2][1], h01.y, w2);
    ffma2(acc[2][2], h23.x, w2); ffma2(acc[2][3], h23.y, w2);
    ffma2(acc[3][0], h01.x, w3); ffma2(acc[3][1], h01.y, w3);
    ffma2(acc[3][2], h23.x, w3); ffma2(acc[3][3], h23.y, w3);
}

// smem layout (floats)
#define OFF_W     0                        // [KDIM][32 j][4 gates] = 36864
#define OFF_HX    36864                    // [256 k][32 b] h + [32 k][32 b] xs = 9216
#define OFF_WOUT  (OFF_HX + 9216)          // [256 j][4 o] = 1024
#define OFF_RED1  (OFF_WOUT + 1024)        // ull[2 side][8 slot][128 thr] = 4096 floats
#define OFF_RED2  (OFF_RED1 + 4096)        // ull[8 slot][256 thr] = 4096 floats
#define OFF_BOUT  (OFF_RED2 + 4096)        // 4 (+4 pad)
#define SMEM_FLOATS (OFF_BOUT + 8)         // 55304 floats = 221,216 B

__global__ void __launch_bounds__(NTHR, 1)
lstm_kernel(const float* __restrict__ x, const float* __restrict__ phys,
            const float* __restrict__ Wih, const float* __restrict__ Whh,
            const float* __restrict__ bih, const float* __restrict__ bhh,
            const float* __restrict__ Wout, const float* __restrict__ bout,
            float* __restrict__ out) {
    extern __shared__ float smem[];
    float* w_s    = smem + OFF_W;
    float* hx     = smem + OFF_HX;          // k-major [k][b], k<256 = h, k>=256 = x
    float* xs     = hx + (HH << 5);         // alias for the x region
    float* wout2  = smem + OFF_WOUT;
    ull*   red1   = (ull*)(smem + OFF_RED1);
    ull*   red2   = (ull*)(smem + OFF_RED2);
    float* bout_s = smem + OFF_BOUT;

    const int tid  = threadIdx.x;
    const int cta  = blockIdx.x;
    const int grp  = cta >> 3;               // batch group 0..15
    const int g8   = cta & 7;                // j-slice 0..7
    const int b0   = grp * BT;
    const int j0   = g8 * JT;
    const int lane = tid & 31;               // lane = j within slice
    const int w    = tid >> 5;               // warp 0..7
    const int oct  = w & 3;                  // batch octet
    const int kh   = w >> 2;                 // k-half / epilogue side

    // ---- one-time: weights [k][j][g] ----
    for (int i = tid; i < KDIM * 128; i += NTHR) {
        int k = i >> 7, r = i & 127;
        int j = r >> 2, g = r & 3;
        int grow = g * HH + j0 + j;
        float v = (k < HH) ? Whh[grow * HH + k] : Wih[grow * II + (k - HH)];
        w_s[(k << 7) + (j << 2) + g] = v;
    }
    for (int i = tid; i < HH * 4; i += NTHR) {
        int k = i >> 2, o = i & 3;
        wout2[(k << 2) + o] = Wout[(g8 * 4 + o) * HH + k];
    }
    if (tid < 4) bout_s[tid] = bout[g8 * 4 + tid];

    // bias (folded into kh=0 accumulator init), packed dup per gate
    ull biasd[4];
#pragma unroll
    for (int g = 0; g < 4; ++g) {
        int gj = g * HH + j0 + lane;
        float bv = bih[gj] + bhh[gj];
        biasd[g] = pack2(bv, bv);
    }

    // ---- prologue: stage xs(0) ----
    {
        float4 xv0 = *(const float4*)(x + (size_t)(b0 + lane) * II + (w << 2));
        xs[((w << 2) + 0) * 32 + lane] = xv0.x;
        xs[((w << 2) + 1) * 32 + lane] = xv0.y;
        xs[((w << 2) + 2) * 32 + lane] = xv0.z;
        xs[((w << 2) + 3) * 32 + lane] = xv0.w;
    }
    __syncthreads();

    const float* wbase = w_s + (lane << 2);
    const float* hb    = hx + (oct << 3);
    const float* xsb   = xs + (oct << 3);

    // acc for step 0: bias (kh=0) + x(0)-part
    ull acc[4][4];
#pragma unroll
    for (int g = 0; g < 4; ++g)
#pragma unroll
        for (int bp = 0; bp < 4; ++bp) acc[g][bp] = kh ? 0ull : biasd[g];
#pragma unroll 4
    for (int kc = kh * 16; kc < kh * 16 + 16; ++kc)
        mac16(acc, wbase + ((HH + kc) << 7), xsb + (kc << 5));

    float c[4] = {0.f, 0.f, 0.f, 0.f};       // cell state: 4 batches per thread

    for (int t = 0; t <= TT; ++t) {
        // ---- per-warp acquire spin on group counter ----
        if (t > 0) {
            if (lane == 0) {
                unsigned target = 8u * (unsigned)t;
                while (ld_acquire_u32(&g_bar[grp]) < target) { }
            }
            __syncwarp();
        }

        // ---- stage h(t) + out-projection partials; stash red2 ----
        {
            ull p2[4][2];
#pragma unroll
            for (int o = 0; o < 4; ++o) { p2[o][0] = 0ull; p2[o][1] = 0ull; }
            const float4* hsrc4 = (const float4*)&g_h[t & 1][grp][0][0];
#pragma unroll
            for (int it = 0; it < 8; ++it) {
                int idx = it * NTHR + tid;
                float4 v = hsrc4[idx];
                int k = idx >> 3, b4 = idx & 7;
                *(float4*)(hx + (k << 5) + (b4 << 2)) = v;
                float4 wo = *(const float4*)(wout2 + (k << 2));
                ull vlo = pack2(v.x, v.y), vhi = pack2(v.z, v.w);
                ull w0 = pack2(wo.x, wo.x), w1 = pack2(wo.y, wo.y);
                ull w2 = pack2(wo.z, wo.z), w3 = pack2(wo.w, wo.w);
                ffma2(p2[0][0], vlo, w0); ffma2(p2[0][1], vhi, w0);
                ffma2(p2[1][0], vlo, w1); ffma2(p2[1][1], vhi, w1);
                ffma2(p2[2][0], vlo, w2); ffma2(p2[2][1], vhi, w2);
                ffma2(p2[3][0], vlo, w3); ffma2(p2[3][1], vhi, w3);
            }
#pragma unroll
            for (int o = 0; o < 4; ++o) {
                red2[(o * 2 + 0) * 256 + tid] = p2[o][0];
                red2[(o * 2 + 1) * 256 + tid] = p2[o][1];
            }
        }
        // early LDG of x(t+1), consumed after the arrive
        float4 xv = make_float4(0.f, 0.f, 0.f, 0.f);
        if (t + 1 < TT)
            xv = *(const float4*)(x + ((size_t)(t + 1) * BB + b0 + lane) * II + (w << 2));
        __syncthreads();

        if (t < TT) {
            // ---- main gate GEMM: k in [kh*128, kh*128+128) over h ----
            const int kbeg = kh << 7;
#pragma unroll 4
            for (int k = kbeg; k < kbeg + 128; ++k)
                mac16(acc, wbase + (k << 7), hb + (k << 5));

            // ---- stash partner's batch-half (conflict-free [side][slot][thr]) ----
            const int idx = tid & 127;
            ull* st = red1 + (size_t)kh * 1024 + idx;
#pragma unroll
            for (int g = 0; g < 4; ++g) {
                st[(g * 2 + 0) * 128] = acc[g][kh ? 0 : 2];
                st[(g * 2 + 1) * 128] = acc[g][kh ? 1 : 3];
            }
        }
        __syncthreads();

        // ---- out-projection finalize for step t-1 (kh=1 warps) ----
        if (kh && t > 0) {
            int u = tid & 127;
            int o = u >> 5, b = u & 31;
            int b4 = b >> 2, bp = (b >> 1) & 1, e = b & 1;
            const ull* rr = red2 + (o * 2 + bp) * 256 + b4;
            ull s = 0ull;
#pragma unroll 8
            for (int m = 0; m < 32; ++m) add2(s, rr[m << 3]);
            float2 sf = unpack2(s);
            float rnn = (e ? sf.y : sf.x) + bout_s[o];
            int tm1 = t - 1, bg = b0 + b, ocl = g8 * 4 + o;
            float ph = phys[((size_t)tm1 * BB + bg) * OO + ocl];
            size_t oi = ((size_t)bg * TT + tm1) * OO + ocl;
            out[oi] = ph + rnn;                               // full_pred [B,T,O]
            out[(size_t)BB * TT * OO + oi] = rnn;             // rnn_pred  [B,T,O]
        }
        if (t == TT) break;

        // ---- symmetric reduce + LSTM epilogue (4 batches per thread) ----
        {
            const int idx = tid & 127;
            const ull* rd = red1 + (size_t)(1 - kh) * 1024 + idx;
            float hv[4];
#pragma unroll
            for (int p = 0; p < 2; ++p) {
                ull s0 = acc[0][kh ? 2 + p : p]; add2(s0, rd[(0 * 2 + p) * 128]);
                ull s1 = acc[1][kh ? 2 + p : p]; add2(s1, rd[(1 * 2 + p) * 128]);
                ull s2 = acc[2][kh ? 2 + p : p]; add2(s2, rd[(2 * 2 + p) * 128]);
                ull s3 = acc[3][kh ? 2 + p : p]; add2(s3, rd[(3 * 2 + p) * 128]);
                float2 gi = unpack2(s0), gf = unpack2(s1);
                float2 gg = unpack2(s2), go = unpack2(s3);
                {
                    float ig = sigf(gi.x), fg = sigf(gf.x);
                    float gt = tanh_acc(gg.x), og = sigf(go.x);
                    float cn = fg * c[p * 2] + ig * gt;
                    c[p * 2] = cn; hv[p * 2] = og * tanh_acc(cn);
                }
                {
                    float ig = sigf(gi.y), fg = sigf(gf.y);
                    float gt = tanh_acc(gg.y), og = sigf(go.y);
                    float cn = fg * c[p * 2 + 1] + ig * gt;
                    c[p * 2 + 1] = cn; hv[p * 2 + 1] = og * tanh_acc(cn);
                }
            }
            float* hd = &g_h[(t + 1) & 1][grp][0][0] + ((j0 + lane) << 5) + (oct << 3) + (kh << 2);
            *(float4*)hd = make_float4(hv[0], hv[1], hv[2], hv[3]);
        }

        // ---- stage xs(t+1); release-arrive; pre-accumulate x-part into acc ----
        if (t + 1 < TT) {
            xs[((w << 2) + 0) * 32 + lane] = xv.x;
            xs[((w << 2) + 1) * 32 + lane] = xv.y;
            xs[((w << 2) + 2) * 32 + lane] = xv.z;
            xs[((w << 2) + 3) * 32 + lane] = xv.w;
        }
        __syncthreads();                      // orders h STG + xs STS before arrive
        if (tid == 0) red_release_add(&g_bar[grp], 1u);

        if (t + 1 < TT) {
#pragma unroll
            for (int g = 0; g < 4; ++g)
#pragma unroll
                for (int bp = 0; bp < 4; ++bp) acc[g][bp] = kh ? 0ull : biasd[g];
#pragma unroll 4
            for (int kc = kh * 16; kc < kh * 16 + 16; ++kc)
                mac16(acc, wbase + ((HH + kc) << 7), xsb + (kc << 5));
        }
    }
}

extern "C" void kernel_launch(void* const* d_in, const int* in_sizes, int n_in,
                              void* d_out, int out_size) {
    const float* x    = (const float*)d_in[0];
    const float* phys = (const float*)d_in[1];
    const float* Wih  = (const float*)d_in[2];
    const float* Whh  = (const float*)d_in[3];
    const float* bih  = (const float*)d_in[4];
    const float* bhh  = (const float*)d_in[5];
    const float* Wout = (const float*)d_in[6];
    const float* bout = (const float*)d_in[7];
    float* out = (float*)d_out;

    size_t smem_bytes = (size_t)SMEM_FLOATS * sizeof(float);   // 221,216 B

    cudaFuncSetAttribute(lstm_kernel,
                         cudaFuncAttributeMaxDynamicSharedMemorySize,
                         (int)smem_bytes);

    init_kernel<<<(NGRP * HH * BT + 255) / 256, 256>>>();
    lstm_kernel<<<NGRP * 8, NTHR, smem_bytes>>>(x, phys, Wih, Whh, bih, bhh,
                                                Wout, bout, out);
}